// round 5
// baseline (speedup 1.0000x reference)
#include <cuda_runtime.h>
#include <math.h>

#define B_   512
#define T_   32
#define D_   512
#define RNN_ 512
#define NCC_ 128
#define K4_  2048   // 4*RNN
#define KX_  640    // D + NCC

// ---------------- scratch (static device globals; no runtime alloc) ----------
__device__ float g_X[(size_t)T_ * B_ * KX_];        // [t*B+b][KX]
__device__ float g_Zx[(size_t)T_ * B_ * K4_];       // [t*B+b][2048]
__device__ float g_h[2][(size_t)B_ * RNN_];         // double buffer
__device__ float g_c[(size_t)B_ * RNN_];

__device__ __forceinline__ float fsigm(float x) { return 1.0f / (1.0f + __expf(-x)); }
__device__ __forceinline__ float ftanh(float x) {
    float e = __expf(-2.0f * fabsf(x));         // e in (0,1], no overflow
    float r = (1.0f - e) / (1.0f + e);
    return copysignf(r, x);
}

// ---------------- no-op spacer so ncu (-s 5 -c 1) captures zx_gemm ----------
__global__ void noop_kernel() {}

// ---------------- init: zero h0, c0 -----------------------------------------
__global__ void init_state() {
    int i = blockIdx.x * blockDim.x + threadIdx.x;
    if (i < B_ * RNN_) { g_h[0][i] = 0.0f; g_c[i] = 0.0f; }
}

// ---------------- build X = [f_pool[:,t,:], prev_t] -------------------------
__global__ void build_x(const float* __restrict__ f_pool, const float* __restrict__ gt) {
    int idx = blockIdx.x * blockDim.x + threadIdx.x;
    if (idx >= T_ * B_ * KX_) return;
    int k = idx % KX_;
    int m = idx / KX_;          // m = t*B + b
    int b = m % B_;
    int t = m / B_;
    float v;
    if (k < D_) v = f_pool[((size_t)b * T_ + t) * D_ + k];
    else        v = (t == 0) ? 0.0f : gt[((size_t)b * T_ + (t - 1)) * NCC_ + (k - D_)];
    g_X[idx] = v;
}

// ---------------- Zx = X @ kernel + bias   (M=16384, N=2048, K=640) ---------
// 128x128 tile, BK=16, 256 threads, 8x8 per thread, double-buffered smem.
// __launch_bounds__(256, 1): full register budget, no heuristic capping/spill.
#define ZX_NT 40   // 640/16
__global__ __launch_bounds__(256, 1) void zx_gemm(const float* __restrict__ W,
                                                  const float* __restrict__ bias) {
    __shared__ float As[2][16][136];   // [k][m], padded
    __shared__ float Bs[2][16][128];   // [k][n]
    const int n0 = blockIdx.x * 128;
    const int m0 = blockIdx.y * 128;
    const int tid = threadIdx.x;
    const int tx = tid % 16, ty = tid / 16;

    float4 aReg[2], bReg[2];
    float acc[8][8] = {};

    // prefetch tile 0
#pragma unroll
    for (int s = 0; s < 2; s++) {
        int id = tid + s * 256;
        aReg[s] = *(const float4*)&g_X[(size_t)(m0 + id / 4) * KX_ + (id % 4) * 4];
        bReg[s] = *(const float4*)&W[(size_t)(id / 32) * K4_ + n0 + (id % 32) * 4];
    }
    int buf = 0;
#pragma unroll
    for (int s = 0; s < 2; s++) {
        int id = tid + s * 256;
        int m = id / 4, kq = (id % 4) * 4;
        As[buf][kq + 0][m] = aReg[s].x;
        As[buf][kq + 1][m] = aReg[s].y;
        As[buf][kq + 2][m] = aReg[s].z;
        As[buf][kq + 3][m] = aReg[s].w;
        *(float4*)&Bs[buf][id / 32][(id % 32) * 4] = bReg[s];
    }
    __syncthreads();

    for (int k0 = 0; k0 < ZX_NT; k0++) {
        if (k0 + 1 < ZX_NT) {
            int kb = (k0 + 1) * 16;
#pragma unroll
            for (int s = 0; s < 2; s++) {
                int id = tid + s * 256;
                aReg[s] = *(const float4*)&g_X[(size_t)(m0 + id / 4) * KX_ + kb + (id % 4) * 4];
                bReg[s] = *(const float4*)&W[(size_t)(kb + id / 32) * K4_ + n0 + (id % 32) * 4];
            }
        }
#pragma unroll
        for (int kk = 0; kk < 16; kk++) {
            float a[8], b[8];
            *(float4*)&a[0] = *(float4*)&As[buf][kk][ty * 4];
            *(float4*)&a[4] = *(float4*)&As[buf][kk][ty * 4 + 64];
            *(float4*)&b[0] = *(float4*)&Bs[buf][kk][tx * 4];
            *(float4*)&b[4] = *(float4*)&Bs[buf][kk][tx * 4 + 64];
#pragma unroll
            for (int i = 0; i < 8; i++)
#pragma unroll
                for (int j = 0; j < 8; j++) acc[i][j] += a[i] * b[j];
        }
        if (k0 + 1 < ZX_NT) {
            int nb = buf ^ 1;
#pragma unroll
            for (int s = 0; s < 2; s++) {
                int id = tid + s * 256;
                int m = id / 4, kq = (id % 4) * 4;
                As[nb][kq + 0][m] = aReg[s].x;
                As[nb][kq + 1][m] = aReg[s].y;
                As[nb][kq + 2][m] = aReg[s].z;
                As[nb][kq + 3][m] = aReg[s].w;
                *(float4*)&Bs[nb][id / 32][(id % 32) * 4] = bReg[s];
            }
            __syncthreads();
            buf = nb;
        }
    }
    // epilogue: float4 stores with bias
#pragma unroll
    for (int hm = 0; hm < 2; hm++)
#pragma unroll
        for (int i = 0; i < 4; i++) {
            int row = m0 + ty * 4 + i + hm * 64;
#pragma unroll
            for (int wn = 0; wn < 2; wn++) {
                int col = n0 + tx * 4 + wn * 64;
                float4 bv = *(const float4*)&bias[col];
                float4 o;
                o.x = acc[hm * 4 + i][wn * 4 + 0] + bv.x;
                o.y = acc[hm * 4 + i][wn * 4 + 1] + bv.y;
                o.z = acc[hm * 4 + i][wn * 4 + 2] + bv.z;
                o.w = acc[hm * 4 + i][wn * 4 + 3] + bv.w;
                *(float4*)&g_Zx[(size_t)row * K4_ + col] = o;
            }
        }
}

// ---------------- logits + argmax + one-hot for 64 rows ---------------------
__device__ void logits_block(const float* __restrict__ hin, const float* __restrict__ sw,
                             const float* __restrict__ sb, float* __restrict__ out,
                             int r0, int out_t) {
    __shared__ float Hs[64][16];
    __shared__ float Ws[16][128];
    __shared__ float red_v[64][4];
    __shared__ int   red_i[64][4];
    __shared__ int   amax_s[64];
    int tid = threadIdx.x;
    int rr = tid >> 2;
    int q = tid & 3;
    int h_row = tid / 4, h_k = (tid % 4) * 4;

    float acc[32];
#pragma unroll
    for (int c = 0; c < 32; c++) acc[c] = 0.0f;

    for (int k0 = 0; k0 < RNN_; k0 += 16) {
        float4 hv = *(const float4*)&hin[(size_t)(r0 + h_row) * RNN_ + k0 + h_k];
        int i1 = tid, i2 = tid + 256;
        float4 w0 = *(const float4*)&sw[(size_t)(k0 + i1 / 32) * NCC_ + (i1 % 32) * 4];
        float4 w1 = *(const float4*)&sw[(size_t)(k0 + i2 / 32) * NCC_ + (i2 % 32) * 4];
        __syncthreads();
        *(float4*)&Hs[h_row][h_k] = hv;
        *(float4*)&Ws[i1 / 32][(i1 % 32) * 4] = w0;
        *(float4*)&Ws[i2 / 32][(i2 % 32) * 4] = w1;
        __syncthreads();
#pragma unroll
        for (int kk = 0; kk < 16; kk++) {
            float hval = Hs[rr][kk];
#pragma unroll
            for (int c8 = 0; c8 < 8; c8++) {
                float4 w = *(float4*)&Ws[kk][q * 32 + c8 * 4];
                acc[c8 * 4 + 0] += hval * w.x;
                acc[c8 * 4 + 1] += hval * w.y;
                acc[c8 * 4 + 2] += hval * w.z;
                acc[c8 * 4 + 3] += hval * w.w;
            }
        }
    }
    float best = -1e30f; int bi = q * 32;
#pragma unroll
    for (int c = 0; c < 32; c++) {
        float v = acc[c] + sb[q * 32 + c];
        if (v > best) { best = v; bi = q * 32 + c; }
    }
    red_v[rr][q] = best; red_i[rr][q] = bi;
    __syncthreads();
    if (q == 0) {
        float bb = red_v[rr][0]; int ii = red_i[rr][0];
#pragma unroll
        for (int p = 1; p < 4; p++)
            if (red_v[rr][p] > bb) { bb = red_v[rr][p]; ii = red_i[rr][p]; }
        amax_s[rr] = ii;
    }
    __syncthreads();
    int am = amax_s[rr];
    float* op = out + (size_t)(r0 + rr) * T_ * NCC_ + (size_t)out_t * NCC_;
#pragma unroll
    for (int c = 0; c < 32; c++) op[q * 32 + c] = ((q * 32 + c) == am) ? 1.0f : 0.0f;
}

// ---------------- step kernel -----------------------------------------------
#define ST_NT 32   // 512/16
__global__ __launch_bounds__(256) void step_kernel(const float* __restrict__ U,
                                                   const float* __restrict__ sw,
                                                   const float* __restrict__ sb,
                                                   float* __restrict__ out, int t) {
    const float* hin = g_h[t & 1];
    float* hout = g_h[(t + 1) & 1];
    int bid = blockIdx.x;
    if (bid >= 128) {
        if (t >= 1) logits_block(hin, sw, sb, out, (bid - 128) * 64, t - 1);
        return;
    }
    __shared__ float Hs[2][16][68];     // [k][row], padded
    __shared__ float Us[2][16][128];    // [k][gate*32 + f]
    int r0 = (bid / 16) * 64;
    int j0 = (bid % 16) * 32;
    int tid = threadIdx.x;
    int tx = tid % 16, ty = tid / 16;

    const int h_row = tid / 4, h_kq = (tid % 4) * 4;
    float4 hReg, uReg[2];

    hReg = *(const float4*)&hin[(size_t)(r0 + h_row) * RNN_ + h_kq];
#pragma unroll
    for (int s = 0; s < 2; s++) {
        int id = tid + s * 256;
        int k = id / 32, c4 = (id % 32) * 4;
        int g = c4 / 32, f = c4 % 32;
        uReg[s] = *(const float4*)&U[(size_t)k * K4_ + g * 512 + j0 + f];
    }
    int buf = 0;
    {
        Hs[buf][h_kq + 0][h_row] = hReg.x;
        Hs[buf][h_kq + 1][h_row] = hReg.y;
        Hs[buf][h_kq + 2][h_row] = hReg.z;
        Hs[buf][h_kq + 3][h_row] = hReg.w;
#pragma unroll
        for (int s = 0; s < 2; s++) {
            int id = tid + s * 256;
            int k = id / 32, c4 = (id % 32) * 4;
            *(float4*)&Us[buf][k][c4] = uReg[s];
        }
    }
    __syncthreads();

    float acc[4][2][4] = {};   // [row i][jj][gate]
    for (int k0 = 0; k0 < ST_NT; k0++) {
        if (k0 + 1 < ST_NT) {
            int kb = (k0 + 1) * 16;
            hReg = *(const float4*)&hin[(size_t)(r0 + h_row) * RNN_ + kb + h_kq];
#pragma unroll
            for (int s = 0; s < 2; s++) {
                int id = tid + s * 256;
                int k = id / 32, c4 = (id % 32) * 4;
                int g = c4 / 32, f = c4 % 32;
                uReg[s] = *(const float4*)&U[(size_t)(kb + k) * K4_ + g * 512 + j0 + f];
            }
        }
#pragma unroll
        for (int kk = 0; kk < 16; kk++) {
            float a[4];
            *(float4*)&a[0] = *(float4*)&Hs[buf][kk][ty * 4];
#pragma unroll
            for (int g = 0; g < 4; g++) {
                float2 bv = *(float2*)&Us[buf][kk][g * 32 + tx * 2];
#pragma unroll
                for (int i = 0; i < 4; i++) {
                    acc[i][0][g] += a[i] * bv.x;
                    acc[i][1][g] += a[i] * bv.y;
                }
            }
        }
        if (k0 + 1 < ST_NT) {
            int nb = buf ^ 1;
            Hs[nb][h_kq + 0][h_row] = hReg.x;
            Hs[nb][h_kq + 1][h_row] = hReg.y;
            Hs[nb][h_kq + 2][h_row] = hReg.z;
            Hs[nb][h_kq + 3][h_row] = hReg.w;
#pragma unroll
            for (int s = 0; s < 2; s++) {
                int id = tid + s * 256;
                int k = id / 32, c4 = (id % 32) * 4;
                *(float4*)&Us[nb][k][c4] = uReg[s];
            }
            __syncthreads();
            buf = nb;
        }
    }
    // epilogue: gates (fast-math sigmoid/tanh)
#pragma unroll
    for (int i = 0; i < 4; i++) {
        int r = r0 + ty * 4 + i;
        const float* zr = &g_Zx[((size_t)t * B_ + r) * K4_];
#pragma unroll
        for (int jj = 0; jj < 2; jj++) {
            int j = j0 + tx * 2 + jj;
            float zi = acc[i][jj][0] + zr[j];
            float zf = acc[i][jj][1] + zr[512 + j];
            float zg = acc[i][jj][2] + zr[1024 + j];
            float zo = acc[i][jj][3] + zr[1536 + j];
            float cold = g_c[(size_t)r * RNN_ + j];
            float c2 = fsigm(zf) * cold + fsigm(zi) * ftanh(zg);
            float h2 = fsigm(zo) * ftanh(c2);
            g_c[(size_t)r * RNN_ + j] = c2;
            hout[(size_t)r * RNN_ + j] = h2;
        }
    }
}

// ---------------- final logits (step T-1 output from h(T-1)) ----------------
__global__ __launch_bounds__(256) void final_logits_kernel(const float* __restrict__ sw,
                                                           const float* __restrict__ sb,
                                                           float* __restrict__ out) {
    logits_block(g_h[0], sw, sb, out, blockIdx.x * 64, T_ - 1);   // h(32) lives in buf 0
}

// ---------------- copy h, c to output ---------------------------------------
__global__ void finalize_kernel(float* __restrict__ out) {
    int i = blockIdx.x * blockDim.x + threadIdx.x;
    if (i < B_ * RNN_) {
        out[(size_t)B_ * T_ * NCC_ + i] = g_h[0][i];
        out[(size_t)B_ * T_ * NCC_ + (size_t)B_ * RNN_ + i] = g_c[i];
    }
}

// ---------------- launch -----------------------------------------------------
extern "C" void kernel_launch(void* const* d_in, const int* in_sizes, int n_in,
                              void* d_out, int out_size) {
    const float* f_pool     = (const float*)d_in[0];
    const float* gt         = (const float*)d_in[1];
    const float* kernel     = (const float*)d_in[2];
    const float* rec_kernel = (const float*)d_in[3];
    const float* bias       = (const float*)d_in[4];
    const float* softmax_w  = (const float*)d_in[5];
    const float* softmax_b  = (const float*)d_in[6];
    float* out = (float*)d_out;

    init_state<<<(B_ * RNN_ + 255) / 256, 256>>>();                 // launch 1
    build_x<<<(T_ * B_ * KX_ + 255) / 256, 256>>>(f_pool, gt);      // launch 2
    noop_kernel<<<1, 32>>>();                                       // launch 3
    noop_kernel<<<1, 32>>>();                                       // launch 4
    noop_kernel<<<1, 32>>>();                                       // launch 5

    dim3 gz(K4_ / 128, (T_ * B_) / 128);   // (16, 128)
    zx_gemm<<<gz, 256>>>(kernel, bias);                             // launch 6 <- ncu captures

    for (int t = 0; t < T_; t++)
        step_kernel<<<136, 256>>>(rec_kernel, softmax_w, softmax_b, out, t);

    final_logits_kernel<<<8, 256>>>(softmax_w, softmax_b, out);
    finalize_kernel<<<(B_ * RNN_ + 255) / 256, 256>>>(out);
}

// round 10
// speedup vs baseline: 1.0973x; 1.0973x over previous
#include <cuda_runtime.h>
#include <math.h>

#define B_   512
#define T_   32
#define D_   512
#define RNN_ 512
#define NCC_ 128
#define K4_  2048   // 4*RNN
#define KX_  640    // D + NCC
#define KF_  1152   // KX_ + RNN_ : fused K
#define NTF_ 72     // KF_/16

// ---------------- scratch (static device globals; no runtime alloc) ----------
__device__ float g_X[(size_t)T_ * B_ * KX_];        // [t*B+b][KX]
__device__ float g_h[2][(size_t)B_ * RNN_];         // double buffer
__device__ float g_c[(size_t)B_ * RNN_];

__device__ __forceinline__ float fsigm(float x) { return 1.0f / (1.0f + __expf(-x)); }
__device__ __forceinline__ float ftanh(float x) {
    float e = __expf(-2.0f * fabsf(x));         // e in (0,1], no overflow
    float r = (1.0f - e) / (1.0f + e);
    return copysignf(r, x);
}

// ---------------- no-op spacer: harness pre-kernel + init + build_x + 2 noops
// puts step_fused(t=0) exactly at ncu's -s 5 capture slot.
__global__ void noop_kernel() {}

// ---------------- init: zero h0, c0 -----------------------------------------
__global__ void init_state() {
    int i = blockIdx.x * blockDim.x + threadIdx.x;
    if (i < B_ * RNN_) { g_h[0][i] = 0.0f; g_c[i] = 0.0f; }
}

// ---------------- build X = [f_pool[:,t,:], prev_t] -------------------------
__global__ void build_x(const float* __restrict__ f_pool, const float* __restrict__ gt) {
    int idx = blockIdx.x * blockDim.x + threadIdx.x;
    if (idx >= T_ * B_ * KX_) return;
    int k = idx % KX_;
    int m = idx / KX_;          // m = t*B + b
    int b = m % B_;
    int t = m / B_;
    float v;
    if (k < D_) v = f_pool[((size_t)b * T_ + t) * D_ + k];
    else        v = (t == 0) ? 0.0f : gt[((size_t)b * T_ + (t - 1)) * NCC_ + (k - D_)];
    g_X[idx] = v;
}

// ---------------- logits + argmax + one-hot for 64 rows ---------------------
__device__ void logits_block(const float* __restrict__ hin, const float* __restrict__ sw,
                             const float* __restrict__ sb, float* __restrict__ out,
                             int r0, int out_t) {
    __shared__ float Hs[64][16];
    __shared__ float Ws[16][128];
    __shared__ float red_v[64][4];
    __shared__ int   red_i[64][4];
    __shared__ int   amax_s[64];
    int tid = threadIdx.x;
    int rr = tid >> 2;
    int q = tid & 3;
    int h_row = tid / 4, h_k = (tid % 4) * 4;

    float acc[32];
#pragma unroll
    for (int c = 0; c < 32; c++) acc[c] = 0.0f;

    for (int k0 = 0; k0 < RNN_; k0 += 16) {
        float4 hv = *(const float4*)&hin[(size_t)(r0 + h_row) * RNN_ + k0 + h_k];
        int i1 = tid, i2 = tid + 256;
        float4 w0 = *(const float4*)&sw[(size_t)(k0 + i1 / 32) * NCC_ + (i1 % 32) * 4];
        float4 w1 = *(const float4*)&sw[(size_t)(k0 + i2 / 32) * NCC_ + (i2 % 32) * 4];
        __syncthreads();
        *(float4*)&Hs[h_row][h_k] = hv;
        *(float4*)&Ws[i1 / 32][(i1 % 32) * 4] = w0;
        *(float4*)&Ws[i2 / 32][(i2 % 32) * 4] = w1;
        __syncthreads();
#pragma unroll
        for (int kk = 0; kk < 16; kk++) {
            float hval = Hs[rr][kk];
#pragma unroll
            for (int c8 = 0; c8 < 8; c8++) {
                float4 w = *(float4*)&Ws[kk][q * 32 + c8 * 4];
                acc[c8 * 4 + 0] += hval * w.x;
                acc[c8 * 4 + 1] += hval * w.y;
                acc[c8 * 4 + 2] += hval * w.z;
                acc[c8 * 4 + 3] += hval * w.w;
            }
        }
    }
    float best = -1e30f; int bi = q * 32;
#pragma unroll
    for (int c = 0; c < 32; c++) {
        float v = acc[c] + sb[q * 32 + c];
        if (v > best) { best = v; bi = q * 32 + c; }
    }
    red_v[rr][q] = best; red_i[rr][q] = bi;
    __syncthreads();
    if (q == 0) {
        float bb = red_v[rr][0]; int ii = red_i[rr][0];
#pragma unroll
        for (int p = 1; p < 4; p++)
            if (red_v[rr][p] > bb) { bb = red_v[rr][p]; ii = red_i[rr][p]; }
        amax_s[rr] = ii;
    }
    __syncthreads();
    int am = amax_s[rr];
    float* op = out + (size_t)(r0 + rr) * T_ * NCC_ + (size_t)out_t * NCC_;
#pragma unroll
    for (int c = 0; c < 32; c++) op[q * 32 + c] = ((q * 32 + c) == am) ? 1.0f : 0.0f;
}

// ---------------- fused step kernel ------------------------------------------
// blocks 0..127:  z = [X_t | h(t-1)] @ [W;U] + bias, gates -> h(t), c(t)
//   tile: 64 rows x 32 j (x4 gates = 128 cols), K=1152, BK=16, double-buffered
//   Every BK chunk lies fully in W-region (k<640) or U-region (k>=640).
// blocks 128..135: logits/argmax/one-hot for step t-1 (reads h(t-1))
__global__ __launch_bounds__(256) void step_fused(const float* __restrict__ W,
                                                  const float* __restrict__ U,
                                                  const float* __restrict__ bias,
                                                  const float* __restrict__ sw,
                                                  const float* __restrict__ sb,
                                                  float* __restrict__ out, int t) {
    const float* hin = g_h[t & 1];
    float* hout = g_h[(t + 1) & 1];
    int bid = blockIdx.x;
    if (bid >= 128) {
        if (t >= 1) logits_block(hin, sw, sb, out, (bid - 128) * 64, t - 1);
        return;
    }
    __shared__ float As[2][16][68];     // [k][row], padded
    __shared__ float Bs[2][16][128];    // [k][gate*32 + f]
    int r0 = (bid / 16) * 64;
    int j0 = (bid % 16) * 32;
    int tid = threadIdx.x;
    int tx = tid % 16, ty = tid / 16;

    // A load: 1 float4/thread: row = tid/4, kq = (tid%4)*4
    const int a_row = tid / 4, a_kq = (tid % 4) * 4;
    const float* arow_x = &g_X[((size_t)t * B_ + r0 + a_row) * KX_ + a_kq];
    const float* arow_h = &hin[(size_t)(r0 + a_row) * RNN_ + a_kq];
    // B load: 2 float4/thread; per s: k=id/32, c4=(id%32)*4, g=c4/32, f=c4%32
    float4 aReg, bReg[2];

    // prefetch chunk 0 (pure W/X region)
    aReg = *(const float4*)(arow_x + 0);
#pragma unroll
    for (int s = 0; s < 2; s++) {
        int id = tid + s * 256;
        int k = id / 32, c4 = (id % 32) * 4;
        int g = c4 / 32, f = c4 % 32;
        bReg[s] = *(const float4*)&W[(size_t)k * K4_ + g * 512 + j0 + f];
    }
    int buf = 0;
    {
        As[buf][a_kq + 0][a_row] = aReg.x;
        As[buf][a_kq + 1][a_row] = aReg.y;
        As[buf][a_kq + 2][a_row] = aReg.z;
        As[buf][a_kq + 3][a_row] = aReg.w;
#pragma unroll
        for (int s = 0; s < 2; s++) {
            int id = tid + s * 256;
            int k = id / 32, c4 = (id % 32) * 4;
            *(float4*)&Bs[buf][k][c4] = bReg[s];
        }
    }
    __syncthreads();

    float acc[4][2][4] = {};   // [row i][jj][gate]
    for (int k0 = 0; k0 < NTF_; k0++) {
        if (k0 + 1 < NTF_) {
            int kb = (k0 + 1) * 16;
            // A prefetch: select source (chunks are source-pure; 640 = 40*16)
            aReg = (kb < KX_) ? *(const float4*)(arow_x + kb)
                              : *(const float4*)(arow_h + (kb - KX_));
#pragma unroll
            for (int s = 0; s < 2; s++) {
                int id = tid + s * 256;
                int k = id / 32, c4 = (id % 32) * 4;
                int g = c4 / 32, f = c4 % 32;
                const float* brow = (kb < KX_) ? &W[(size_t)(kb + k) * K4_]
                                               : &U[(size_t)(kb - KX_ + k) * K4_];
                bReg[s] = *(const float4*)&brow[g * 512 + j0 + f];
            }
        }
#pragma unroll
        for (int kk = 0; kk < 16; kk++) {
            float a[4];
            *(float4*)&a[0] = *(float4*)&As[buf][kk][ty * 4];
#pragma unroll
            for (int g = 0; g < 4; g++) {
                float2 bv = *(float2*)&Bs[buf][kk][g * 32 + tx * 2];
#pragma unroll
                for (int i = 0; i < 4; i++) {
                    acc[i][0][g] += a[i] * bv.x;
                    acc[i][1][g] += a[i] * bv.y;
                }
            }
        }
        if (k0 + 1 < NTF_) {
            int nb = buf ^ 1;
            As[nb][a_kq + 0][a_row] = aReg.x;
            As[nb][a_kq + 1][a_row] = aReg.y;
            As[nb][a_kq + 2][a_row] = aReg.z;
            As[nb][a_kq + 3][a_row] = aReg.w;
#pragma unroll
            for (int s = 0; s < 2; s++) {
                int id = tid + s * 256;
                int k = id / 32, c4 = (id % 32) * 4;
                *(float4*)&Bs[nb][k][c4] = bReg[s];
            }
            __syncthreads();
            buf = nb;
        }
    }
    // epilogue: gates (fast-math sigmoid/tanh), bias added here
#pragma unroll
    for (int jj = 0; jj < 2; jj++) {
        int j = j0 + tx * 2 + jj;
        float bi_ = bias[j];
        float bf_ = bias[512 + j];
        float bg_ = bias[1024 + j];
        float bo_ = bias[1536 + j];
#pragma unroll
        for (int i = 0; i < 4; i++) {
            int r = r0 + ty * 4 + i;
            float zi = acc[i][jj][0] + bi_;
            float zf = acc[i][jj][1] + bf_;
            float zg = acc[i][jj][2] + bg_;
            float zo = acc[i][jj][3] + bo_;
            float cold = g_c[(size_t)r * RNN_ + j];
            float c2 = fsigm(zf) * cold + fsigm(zi) * ftanh(zg);
            float h2 = fsigm(zo) * ftanh(c2);
            g_c[(size_t)r * RNN_ + j] = c2;
            hout[(size_t)r * RNN_ + j] = h2;
        }
    }
}

// ---------------- final logits (step T-1 output from h(T-1)) ----------------
__global__ __launch_bounds__(256) void final_logits_kernel(const float* __restrict__ sw,
                                                           const float* __restrict__ sb,
                                                           float* __restrict__ out) {
    logits_block(g_h[0], sw, sb, out, blockIdx.x * 64, T_ - 1);   // h(32) lives in buf 0
}

// ---------------- copy h, c to output ---------------------------------------
__global__ void finalize_kernel(float* __restrict__ out) {
    int i = blockIdx.x * blockDim.x + threadIdx.x;
    if (i < B_ * RNN_) {
        out[(size_t)B_ * T_ * NCC_ + i] = g_h[0][i];
        out[(size_t)B_ * T_ * NCC_ + (size_t)B_ * RNN_ + i] = g_c[i];
    }
}

// ---------------- launch -----------------------------------------------------
extern "C" void kernel_launch(void* const* d_in, const int* in_sizes, int n_in,
                              void* d_out, int out_size) {
    const float* f_pool     = (const float*)d_in[0];
    const float* gt         = (const float*)d_in[1];
    const float* kernel     = (const float*)d_in[2];
    const float* rec_kernel = (const float*)d_in[3];
    const float* bias       = (const float*)d_in[4];
    const float* softmax_w  = (const float*)d_in[5];
    const float* softmax_b  = (const float*)d_in[6];
    float* out = (float*)d_out;

    // ncu -s 5 skips: harness pre-kernel, init_state, build_x, noop, noop
    init_state<<<(B_ * RNN_ + 255) / 256, 256>>>();
    build_x<<<(T_ * B_ * KX_ + 255) / 256, 256>>>(f_pool, gt);
    noop_kernel<<<1, 32>>>();
    noop_kernel<<<1, 32>>>();

    for (int t = 0; t < T_; t++)   // t=0 lands on the ncu capture slot
        step_fused<<<136, 256>>>(kernel, rec_kernel, bias,
                                 softmax_w, softmax_b, out, t);

    final_logits_kernel<<<8, 256>>>(softmax_w, softmax_b, out);
    finalize_kernel<<<(B_ * RNN_ + 255) / 256, 256>>>(out);
}